// round 6
// baseline (speedup 1.0000x reference)
#include <cuda_runtime.h>
#include <cuda_bf16.h>
#include <math.h>
#include <stdint.h>

#define FEAT     256
#define NMOL     1024
#define TM       64
#define NTHREADS 512            // 16 warps: 2 (M) x 8 (N)
#define NCTA     152
#define WIMG_B   65536          // one fp8 weight image (256 n-rows x 256 k-bytes)
#define A_BYTES  (TM * 256)     // 16384 fp8 A tile
#define STAGE_B  (TM * FEAT * 4) // 65536 fp32 X staging

__device__ __constant__ float kScale = 5.992277830325989f;
__device__ __constant__ float kShift = -406274.63784969115f;

__device__ __align__(128) unsigned char g_Wimg[2][WIMG_B];
__device__ int g_is64;

// ---------------------------------------------------------------------------
__device__ __forceinline__ uint32_t smem_u32(const void* p) {
    uint32_t a;
    asm("{ .reg .u64 t; cvta.to.shared.u64 t, %1; cvt.u32.u64 %0, t; }" : "=r"(a) : "l"(p));
    return a;
}
#define MBARRIER_INIT(addr, cnt) \
    asm volatile("mbarrier.init.shared.b64 [%0], %1;" :: "r"(addr), "r"(cnt) : "memory")
#define MBARRIER_EXPECT_TX(addr, bytes) \
    asm volatile("mbarrier.arrive.expect_tx.shared.b64 _, [%0], %1;" :: "r"(addr), "r"(bytes) : "memory")
#define MBARRIER_WAIT_PARITY(addr, ph) do { \
    uint32_t _m = (addr); uint32_t _p = (ph); uint32_t _d; \
    asm volatile("{ .reg .pred p; mbarrier.try_wait.parity.acquire.cta.shared::cta.b64 p, [%1], %2; selp.b32 %0,1,0,p; }" \
        : "=r"(_d) : "r"(_m), "r"(_p) : "memory"); \
    if (!_d) { asm volatile("{ .reg .pred P1; WL_%=: mbarrier.try_wait.parity.acquire.cta.shared::cta.b64 P1, [%0], %1, 0x989680; @P1 bra.uni WD_%=; bra.uni WL_%=; WD_%=: }" \
        :: "r"(_m), "r"(_p) : "memory"); } \
} while (0)
#define FENCE_PROXY_ASYNC() asm volatile("fence.proxy.async.shared::cta;" ::: "memory")
#define CP_COMMIT() asm volatile("cp.async.commit_group;" ::: "memory")
#define CP_WAIT0()  asm volatile("cp.async.wait_group 0;" ::: "memory")

__device__ __forceinline__ void bulk_g2s(uint32_t dst, const void* src, uint32_t bytes, uint32_t mbar) {
    asm volatile("cp.async.bulk.shared::cta.global.mbarrier::complete_tx::bytes [%0], [%1], %2, [%3];"
                 :: "r"(dst), "l"(src), "r"(bytes), "r"(mbar) : "memory");
}
__device__ __forceinline__ void cp_async16(uint32_t dst, const void* src, uint32_t src_sz) {
    asm volatile("cp.async.cg.shared.global [%0], [%1], 16, %2;"
                 :: "r"(dst), "l"(src), "r"(src_sz) : "memory");
}
__device__ __forceinline__ void ldsm_x4(uint32_t* r, uint32_t addr) {
    asm volatile("ldmatrix.sync.aligned.m8n8.x4.shared.b16 {%0,%1,%2,%3}, [%4];"
                 : "=r"(r[0]), "=r"(r[1]), "=r"(r[2]), "=r"(r[3]) : "r"(addr));
}
__device__ __forceinline__ void mma_fp8(float* c, const uint32_t* a, uint32_t b0, uint32_t b1) {
    asm volatile("mma.sync.aligned.m16n8k32.row.col.f32.e4m3.e4m3.f32 "
                 "{%0,%1,%2,%3}, {%4,%5,%6,%7}, {%8,%9}, {%0,%1,%2,%3};"
                 : "+f"(c[0]), "+f"(c[1]), "+f"(c[2]), "+f"(c[3])
                 : "r"(a[0]), "r"(a[1]), "r"(a[2]), "r"(a[3]), "r"(b0), "r"(b1));
}
__device__ __forceinline__ unsigned short f2e4m3x2(float lo, float hi) {
    unsigned short t;
    asm("cvt.rn.satfinite.e4m3x2.f32 %0, %1, %2;" : "=h"(t) : "f"(hi), "f"(lo));
    return t;
}
__device__ __forceinline__ float fast_silu(float x) {
    float t;
    asm("tanh.approx.f32 %0, %1;" : "=f"(t) : "f"(0.5f * x));
    return x * (0.5f * t + 0.5f);
}
__device__ __forceinline__ uint32_t swz(int r, int cbyte) {
    return (uint32_t)(r * 256 + ((((cbyte >> 4) ^ (r & 7)) << 4) | (cbyte & 15)));
}

// ---------------------------------------------------------------------------
// Prep: W -> fp8 swizzled n-major images + out init + batch dtype probe
// ---------------------------------------------------------------------------
__global__ void prep(const float* __restrict__ W1, const float* __restrict__ W2,
                     const void* __restrict__ batch, float* __restrict__ out) {
    __shared__ float s[32][33];
    int tile = blockIdx.x;
    int k0 = (tile >> 3) * 32, n0 = (tile & 7) * 32;
    const float* W = blockIdx.y ? W2 : W1;
    unsigned char* img = g_Wimg[blockIdx.y];
    int t = threadIdx.x;
    {
        int kk = t >> 3, nn = (t & 7) * 4;
        float4 v = *(const float4*)&W[(k0 + kk) * FEAT + n0 + nn];
        s[kk][nn] = v.x; s[kk][nn + 1] = v.y; s[kk][nn + 2] = v.z; s[kk][nn + 3] = v.w;
    }
    __syncthreads();
    {
        int nn = t >> 3, kk = (t & 7) * 4;
        int n = n0 + nn, k = k0 + kk;
        unsigned short p0 = f2e4m3x2(s[kk][nn],     s[kk + 1][nn]);
        unsigned short p1 = f2e4m3x2(s[kk + 2][nn], s[kk + 3][nn]);
        *(uint32_t*)(img + swz(n, k)) = (uint32_t)p0 | ((uint32_t)p1 << 16);
    }
    if (blockIdx.y == 0 && blockIdx.x < 4) {
        int gi = blockIdx.x * 256 + t;
        out[gi] = kShift;
        if (gi == 0) {
            const int* w = (const int*)batch;
            g_is64 = (w[1001] == 0 && w[1000] > 0) ? 1 : 0;
        }
    }
}
__device__ __forceinline__ int load_mol(const void* batch, int i) {
    if (g_is64) return (int)((const long long*)batch)[i];
    return ((const int*)batch)[i];
}

// ---------------------------------------------------------------------------
// smem layout
// ---------------------------------------------------------------------------
#define OFF_A     0
#define OFF_W     (OFF_A + A_BYTES)            // 16384
#define OFF_STAGE (OFF_W + 2 * WIMG_B)         // 147456
#define OFF_B1    (OFF_STAGE + STAGE_B)        // 212992
#define OFF_B2    (OFF_B1 + 1024)
#define OFF_W3    (OFF_B2 + 1024)
#define OFF_MOL   (OFF_W3 + 1024)              // 4096
#define OFF_ROW   (OFF_MOL + 4096)             // 256
#define OFF_MBAR  (OFF_ROW + 256)
#define SMEM_BYTES (OFF_MBAR + 8 + 128)

// issue cp.async for one X tile into stage (zero-fill past n_atoms)
__device__ __forceinline__ void issue_x(uint32_t stage_u, const float* __restrict__ X,
                                        int row0, int n_atoms, int tid) {
#pragma unroll
    for (int i = 0; i < 8; i++) {
        int idx = tid * 4 + i * 2048;          // element index in 64x256 tile
        int r = idx >> 8;
        int grow = row0 + r;
        uint32_t zf = (grow < n_atoms) ? 16u : 0u;
        cp_async16(stage_u + idx * 4, X + (size_t)grow * FEAT + (idx & 255), zf);
    }
    CP_COMMIT();
}
// stage (fp32 smem) -> fp8 swizzled A
__device__ __forceinline__ void store_x(const char* s_stage, char* s_A, int tid) {
#pragma unroll
    for (int i = 0; i < 8; i++) {
        int idx = tid * 4 + i * 2048;
        int r = idx >> 8, c = idx & 255;
        float4 v = *(const float4*)(s_stage + idx * 4);
        unsigned short p0 = f2e4m3x2(v.x, v.y);
        unsigned short p1 = f2e4m3x2(v.z, v.w);
        *(uint32_t*)(s_A + swz(r, c)) = (uint32_t)p0 | ((uint32_t)p1 << 16);
    }
}

// 32x32 per-warp FP8 GEMM, fragment-pipelined
__device__ __forceinline__ void gemm_fp8(float acc[2][4][4], uint32_t A_u, uint32_t W_u,
                                         int wm, int wn, int lane) {
    const int rowA = wm * 32 + (lane & 7) + ((lane >> 3) & 1) * 8;
    const int gA   = lane >> 4;
    const int rxA  = rowA & 7;
    const uint32_t baseA = A_u + rowA * 256;
    const int rowB = wn * 32 + (lane >> 4) * 8 + (lane & 7);
    const int gB   = (lane >> 3) & 1;
    const int rxB  = rowB & 7;
    const uint32_t baseB = W_u + rowB * 256;

    uint32_t a0[2][4], a1[2][4], b0[2][4], b1[2][4];
#define LOADF(s, buf) do { \
        uint32_t oA = (uint32_t)(((2 * (s) + gA) ^ rxA) << 4); \
        uint32_t oB = (uint32_t)(((2 * (s) + gB) ^ rxB) << 4); \
        ldsm_x4(a0[buf], baseA + oA); \
        ldsm_x4(a1[buf], baseA + 16 * 256 + oA); \
        ldsm_x4(b0[buf], baseB + oB); \
        ldsm_x4(b1[buf], baseB + 16 * 256 + oB); } while (0)

    LOADF(0, 0);
#pragma unroll
    for (int s = 0; s < 8; s++) {
        const int cur = s & 1;
        if (s < 7) LOADF(s + 1, cur ^ 1);      // prefetch next fragments
        mma_fp8(acc[0][0], a0[cur], b0[cur][0], b0[cur][1]);
        mma_fp8(acc[1][0], a1[cur], b0[cur][0], b0[cur][1]);
        mma_fp8(acc[0][1], a0[cur], b0[cur][2], b0[cur][3]);
        mma_fp8(acc[1][1], a1[cur], b0[cur][2], b0[cur][3]);
        mma_fp8(acc[0][2], a0[cur], b1[cur][0], b1[cur][1]);
        mma_fp8(acc[1][2], a1[cur], b1[cur][0], b1[cur][1]);
        mma_fp8(acc[0][3], a0[cur], b1[cur][2], b1[cur][3]);
        mma_fp8(acc[1][3], a1[cur], b1[cur][2], b1[cur][3]);
    }
#undef LOADF
}

__global__ void __launch_bounds__(NTHREADS, 1)
fused_mlp(const float* __restrict__ X, const void* __restrict__ batch,
          const float* __restrict__ b1, const float* __restrict__ b2,
          const float* __restrict__ W3, const float* __restrict__ b3,
          float* __restrict__ out, int n_atoms) {
    extern __shared__ char sraw[];
    uint32_t sb = smem_u32(sraw);
    uint32_t wb = (sb + 127) & ~127u;
    char* base = sraw + (wb - sb);

    char*  s_A     = base + OFF_A;
    char*  s_stage = base + OFF_STAGE;
    float* b1s     = (float*)(base + OFF_B1);
    float* b2s     = (float*)(base + OFF_B2);
    float* w3s     = (float*)(base + OFF_W3);
    float* molacc  = (float*)(base + OFF_MOL);
    float* rowsum  = (float*)(base + OFF_ROW);
    const uint32_t mbar = wb + OFF_MBAR;
    const uint32_t A_u = wb + OFF_A, W_u = wb + OFF_W, ST_u = wb + OFF_STAGE;

    const int tid = threadIdx.x;
    const int wid = tid >> 5, lane = tid & 31;
    const int wm = wid >> 3, wn = wid & 7;
    const int g = lane >> 2, q = lane & 3;
    const int stride = gridDim.x * TM;

    if (tid == 0) {
        MBARRIER_INIT(mbar, 1);
        FENCE_PROXY_ASYNC();
        MBARRIER_EXPECT_TX(mbar, 2 * WIMG_B);
        bulk_g2s(W_u, &g_Wimg[0][0], 2 * WIMG_B, mbar);
    }
    for (int i = tid; i < NMOL; i += NTHREADS) molacc[i] = 0.0f;
    if (tid < TM) rowsum[tid] = 0.0f;
    if (tid < FEAT) { b1s[tid] = b1[tid]; b2s[tid] = b2[tid]; w3s[tid] = W3[tid]; }
    const float b3v = *b3;

    int row0 = blockIdx.x * TM;
    issue_x(ST_u, X, row0, n_atoms, tid);       // tile 0 staging
    __syncthreads();                            // mbarrier init visible
    MBARRIER_WAIT_PARITY(mbar, 0);              // weights resident forever

    while (row0 < n_atoms) {
        CP_WAIT0();                             // my staged slice ready
        store_x(s_stage, s_A, tid);
        __syncthreads();                        // A ready

        const int next_row0 = row0 + stride;
        if (next_row0 < n_atoms)                // prefetch next tile into stage
            issue_x(ST_u, X, next_row0, n_atoms, tid);
        else
            CP_COMMIT();                        // keep group count consistent

        // ---- layer 1 ----
        float acc[2][4][4];
#pragma unroll
        for (int mi = 0; mi < 2; mi++)
#pragma unroll
            for (int ni = 0; ni < 4; ni++)
#pragma unroll
                for (int j = 0; j < 4; j++) acc[mi][ni][j] = 0.0f;
        gemm_fp8(acc, A_u, W_u, wm, wn, lane);
        __syncthreads();                        // A consumed

        // ---- epilogue 1: bias + silu -> fp8 back into A ----
#pragma unroll
        for (int mi = 0; mi < 2; mi++) {
            int r0 = wm * 32 + mi * 16 + g;
#pragma unroll
            for (int ni = 0; ni < 4; ni++) {
                int c0 = wn * 32 + ni * 8 + 2 * q;
                float bb0 = b1s[c0], bb1 = b1s[c0 + 1];
                unsigned short h0 = f2e4m3x2(fast_silu(acc[mi][ni][0] + bb0),
                                             fast_silu(acc[mi][ni][1] + bb1));
                unsigned short h1 = f2e4m3x2(fast_silu(acc[mi][ni][2] + bb0),
                                             fast_silu(acc[mi][ni][3] + bb1));
                *(unsigned short*)(s_A + swz(r0, c0))     = h0;
                *(unsigned short*)(s_A + swz(r0 + 8, c0)) = h1;
#pragma unroll
                for (int j = 0; j < 4; j++) acc[mi][ni][j] = 0.0f;
            }
        }
        __syncthreads();                        // A2 ready

        // ---- layer 2 ----
        gemm_fp8(acc, A_u, W_u + WIMG_B, wm, wn, lane);

        // ---- epilogue 2: bias + silu + dot(W3) ----
#pragma unroll
        for (int mi = 0; mi < 2; mi++) {
            float p0 = 0.0f, p1 = 0.0f;
#pragma unroll
            for (int ni = 0; ni < 4; ni++) {
                int c0 = wn * 32 + ni * 8 + 2 * q;
                float bb0 = b2s[c0], bb1 = b2s[c0 + 1];
                float w0 = w3s[c0], w1 = w3s[c0 + 1];
                p0 += fast_silu(acc[mi][ni][0] + bb0) * w0 + fast_silu(acc[mi][ni][1] + bb1) * w1;
                p1 += fast_silu(acc[mi][ni][2] + bb0) * w0 + fast_silu(acc[mi][ni][3] + bb1) * w1;
            }
            p0 += __shfl_xor_sync(0xffffffffu, p0, 1); p0 += __shfl_xor_sync(0xffffffffu, p0, 2);
            p1 += __shfl_xor_sync(0xffffffffu, p1, 1); p1 += __shfl_xor_sync(0xffffffffu, p1, 2);
            if (q == 0) {
                int r0 = wm * 32 + mi * 16 + g;
                atomicAdd(&rowsum[r0], p0);
                atomicAdd(&rowsum[r0 + 8], p1);
            }
        }
        __syncthreads();                        // rowsum ready; A consumed

        // ---- pooling ----
        if (tid < TM) {
            int grow = row0 + tid;
            if (grow < n_atoms) {
                int mol = load_mol(batch, grow);
                atomicAdd(&molacc[mol], rowsum[tid] + b3v);
            }
            rowsum[tid] = 0.0f;
        }
        row0 = next_row0;
    }

    __syncthreads();
    for (int i = tid; i < NMOL; i += NTHREADS) {
        float v = molacc[i];
        if (v != 0.0f) atomicAdd(out + i, v * kScale);
    }
}

// ---------------------------------------------------------------------------
extern "C" void kernel_launch(void* const* d_in, const int* in_sizes, int n_in,
                              void* d_out, int out_size) {
    const float* atom_node = (const float*)d_in[0];
    const void*  batch     = d_in[1];
    const float* W1 = (const float*)d_in[2];
    const float* b1 = (const float*)d_in[3];
    const float* W2 = (const float*)d_in[4];
    const float* b2 = (const float*)d_in[5];
    const float* W3 = (const float*)d_in[6];
    const float* b3 = (const float*)d_in[7];
    float* out = (float*)d_out;
    const int n_atoms = in_sizes[1];

    prep<<<dim3(64, 2), 256>>>(W1, W2, batch, out);

    cudaFuncSetAttribute(fused_mlp, cudaFuncAttributeMaxDynamicSharedMemorySize, SMEM_BYTES);
    int ntiles = (n_atoms + TM - 1) / TM;
    int grid = ntiles < NCTA ? ntiles : NCTA;
    fused_mlp<<<grid, NTHREADS, SMEM_BYTES>>>(atom_node, batch, b1, b2, W3, b3, out, n_atoms);
}

// round 7
// speedup vs baseline: 1.1191x; 1.1191x over previous
#include <cuda_runtime.h>
#include <cuda_bf16.h>
#include <math.h>
#include <stdint.h>

#define FEAT     256
#define NMOL     1024
#define TM       32              // rows per group tile
#define NTHREADS 512             // 2 groups x 8 warps
#define NCTA     152
#define WIMG_B   65536           // one fp8 weight image
#define A_G      8192            // fp8 A tile per group (32x256)
#define STAGE_G  32768           // fp32 stage per group (32x256)

__device__ __constant__ float kScale = 5.992277830325989f;
__device__ __constant__ float kShift = -406274.63784969115f;

__device__ __align__(128) unsigned char g_Wimg[2][WIMG_B];
__device__ int g_is64;

// ---------------------------------------------------------------------------
__device__ __forceinline__ uint32_t smem_u32(const void* p) {
    uint32_t a;
    asm("{ .reg .u64 t; cvta.to.shared.u64 t, %1; cvt.u32.u64 %0, t; }" : "=r"(a) : "l"(p));
    return a;
}
#define MBARRIER_INIT(addr, cnt) \
    asm volatile("mbarrier.init.shared.b64 [%0], %1;" :: "r"(addr), "r"(cnt) : "memory")
#define MBARRIER_EXPECT_TX(addr, bytes) \
    asm volatile("mbarrier.arrive.expect_tx.shared.b64 _, [%0], %1;" :: "r"(addr), "r"(bytes) : "memory")
#define MBARRIER_WAIT_PARITY(addr, ph) do { \
    uint32_t _m = (addr); uint32_t _p = (ph); uint32_t _d; \
    asm volatile("{ .reg .pred p; mbarrier.try_wait.parity.acquire.cta.shared::cta.b64 p, [%1], %2; selp.b32 %0,1,0,p; }" \
        : "=r"(_d) : "r"(_m), "r"(_p) : "memory"); \
    if (!_d) { asm volatile("{ .reg .pred P1; WL_%=: mbarrier.try_wait.parity.acquire.cta.shared::cta.b64 P1, [%0], %1, 0x989680; @P1 bra.uni WD_%=; bra.uni WL_%=; WD_%=: }" \
        :: "r"(_m), "r"(_p) : "memory"); } \
} while (0)
#define FENCE_PROXY_ASYNC() asm volatile("fence.proxy.async.shared::cta;" ::: "memory")
#define CP_COMMIT() asm volatile("cp.async.commit_group;" ::: "memory")
#define CP_WAIT0()  asm volatile("cp.async.wait_group 0;" ::: "memory")
#define BAR_SYNC(id) asm volatile("bar.sync %0, 256;" :: "r"(id) : "memory")

__device__ __forceinline__ void bulk_g2s(uint32_t dst, const void* src, uint32_t bytes, uint32_t mbar) {
    asm volatile("cp.async.bulk.shared::cta.global.mbarrier::complete_tx::bytes [%0], [%1], %2, [%3];"
                 :: "r"(dst), "l"(src), "r"(bytes), "r"(mbar) : "memory");
}
__device__ __forceinline__ void cp_async16(uint32_t dst, const void* src, uint32_t src_sz) {
    asm volatile("cp.async.cg.shared.global [%0], [%1], 16, %2;"
                 :: "r"(dst), "l"(src), "r"(src_sz) : "memory");
}
__device__ __forceinline__ void ldsm_x4(uint32_t* r, uint32_t addr) {
    asm volatile("ldmatrix.sync.aligned.m8n8.x4.shared.b16 {%0,%1,%2,%3}, [%4];"
                 : "=r"(r[0]), "=r"(r[1]), "=r"(r[2]), "=r"(r[3]) : "r"(addr));
}
__device__ __forceinline__ void mma_fp8(float* c, const uint32_t* a, uint32_t b0, uint32_t b1) {
    asm volatile("mma.sync.aligned.m16n8k32.row.col.f32.e4m3.e4m3.f32 "
                 "{%0,%1,%2,%3}, {%4,%5,%6,%7}, {%8,%9}, {%0,%1,%2,%3};"
                 : "+f"(c[0]), "+f"(c[1]), "+f"(c[2]), "+f"(c[3])
                 : "r"(a[0]), "r"(a[1]), "r"(a[2]), "r"(a[3]), "r"(b0), "r"(b1));
}
__device__ __forceinline__ unsigned short f2e4m3x2(float lo, float hi) {
    unsigned short t;
    asm("cvt.rn.satfinite.e4m3x2.f32 %0, %1, %2;" : "=h"(t) : "f"(hi), "f"(lo));
    return t;
}
__device__ __forceinline__ float fast_silu(float x) {
    float t;
    asm("tanh.approx.f32 %0, %1;" : "=f"(t) : "f"(0.5f * x));
    return x * (0.5f * t + 0.5f);
}
__device__ __forceinline__ uint32_t swz(int r, int cbyte) {
    return (uint32_t)(r * 256 + ((((cbyte >> 4) ^ (r & 7)) << 4) | (cbyte & 15)));
}

// ---------------------------------------------------------------------------
// Prep: W -> fp8 swizzled n-major images + out init + batch dtype probe
// ---------------------------------------------------------------------------
__global__ void prep(const float* __restrict__ W1, const float* __restrict__ W2,
                     const void* __restrict__ batch, float* __restrict__ out) {
    __shared__ float s[32][33];
    int tile = blockIdx.x;
    int k0 = (tile >> 3) * 32, n0 = (tile & 7) * 32;
    const float* W = blockIdx.y ? W2 : W1;
    unsigned char* img = g_Wimg[blockIdx.y];
    int t = threadIdx.x;
    {
        int kk = t >> 3, nn = (t & 7) * 4;
        float4 v = *(const float4*)&W[(k0 + kk) * FEAT + n0 + nn];
        s[kk][nn] = v.x; s[kk][nn + 1] = v.y; s[kk][nn + 2] = v.z; s[kk][nn + 3] = v.w;
    }
    __syncthreads();
    {
        int nn = t >> 3, kk = (t & 7) * 4;
        int n = n0 + nn, k = k0 + kk;
        unsigned short p0 = f2e4m3x2(s[kk][nn],     s[kk + 1][nn]);
        unsigned short p1 = f2e4m3x2(s[kk + 2][nn], s[kk + 3][nn]);
        *(uint32_t*)(img + swz(n, k)) = (uint32_t)p0 | ((uint32_t)p1 << 16);
    }
    if (blockIdx.y == 0 && blockIdx.x < 4) {
        int gi = blockIdx.x * 256 + t;
        out[gi] = kShift;
        if (gi == 0) {
            const int* w = (const int*)batch;
            g_is64 = (w[1001] == 0 && w[1000] > 0) ? 1 : 0;
        }
    }
}
__device__ __forceinline__ int load_mol(const void* batch, int i) {
    if (g_is64) return (int)((const long long*)batch)[i];
    return ((const int*)batch)[i];
}

// ---------------------------------------------------------------------------
// smem layout
// ---------------------------------------------------------------------------
#define OFF_W     0
#define OFF_A     (OFF_W + 2 * WIMG_B)        // 131072 : 2 x 8192
#define OFF_STAGE (OFF_A + 2 * A_G)           // 147456 : 2 x 32768
#define OFF_B1    (OFF_STAGE + 2 * STAGE_G)   // 212992
#define OFF_B2    (OFF_B1 + 1024)
#define OFF_W3    (OFF_B2 + 1024)
#define OFF_MOL   (OFF_W3 + 1024)             // 4096
#define OFF_ROW   (OFF_MOL + 4096)            // 2 x 128
#define OFF_MBAR  (OFF_ROW + 256)
#define SMEM_BYTES (OFF_MBAR + 8 + 128)

// issue cp.async for one 32x256 X tile into this group's stage
__device__ __forceinline__ void issue_x(uint32_t stage_u, const float* __restrict__ X,
                                        int row0, int n_atoms, int gt) {
#pragma unroll
    for (int i = 0; i < 8; i++) {
        int idx = gt * 4 + i * 1024;           // element index in 32x256 tile
        int r = idx >> 8;
        int grow = row0 + r;
        uint32_t zf = (grow < n_atoms) ? 16u : 0u;
        cp_async16(stage_u + idx * 4, X + (size_t)grow * FEAT + (idx & 255), zf);
    }
    CP_COMMIT();
}
__device__ __forceinline__ void store_x(const char* s_stage, char* s_A, int gt) {
#pragma unroll
    for (int i = 0; i < 8; i++) {
        int idx = gt * 4 + i * 1024;
        int r = idx >> 8, c = idx & 255;
        float4 v = *(const float4*)(s_stage + idx * 4);
        unsigned short p0 = f2e4m3x2(v.x, v.y);
        unsigned short p1 = f2e4m3x2(v.z, v.w);
        *(uint32_t*)(s_A + swz(r, c)) = (uint32_t)p0 | ((uint32_t)p1 << 16);
    }
}

// 32(rows) x 32(cols) per-warp FP8 GEMM over k=256
__device__ __forceinline__ void gemm_fp8(float acc[2][4][4], uint32_t A_u, uint32_t W_u,
                                         int wn, int lane) {
    const int rowA = (lane & 7) + ((lane >> 3) & 1) * 8;
    const int gA   = lane >> 4;
    const int rxA  = rowA & 7;
    const uint32_t baseA = A_u + rowA * 256;
    const int rowB = wn * 32 + (lane >> 4) * 8 + (lane & 7);
    const int gB   = (lane >> 3) & 1;
    const int rxB  = rowB & 7;
    const uint32_t baseB = W_u + rowB * 256;
#pragma unroll
    for (int s = 0; s < 8; s++) {
        uint32_t a0[4], a1[4], b0[4], b1[4];
        uint32_t oA = (uint32_t)(((2 * s + gA) ^ rxA) << 4);
        uint32_t oB = (uint32_t)(((2 * s + gB) ^ rxB) << 4);
        ldsm_x4(a0, baseA + oA);                 // rows 0..15
        ldsm_x4(a1, baseA + 16 * 256 + oA);      // rows 16..31
        ldsm_x4(b0, baseB + oB);                 // cols wn*32 .. +15
        ldsm_x4(b1, baseB + 16 * 256 + oB);      // cols +16 .. +31
        mma_fp8(acc[0][0], a0, b0[0], b0[1]);
        mma_fp8(acc[1][0], a1, b0[0], b0[1]);
        mma_fp8(acc[0][1], a0, b0[2], b0[3]);
        mma_fp8(acc[1][1], a1, b0[2], b0[3]);
        mma_fp8(acc[0][2], a0, b1[0], b1[1]);
        mma_fp8(acc[1][2], a1, b1[0], b1[1]);
        mma_fp8(acc[0][3], a0, b1[2], b1[3]);
        mma_fp8(acc[1][3], a1, b1[2], b1[3]);
    }
}

__global__ void __launch_bounds__(NTHREADS, 1)
fused_mlp(const float* __restrict__ X, const void* __restrict__ batch,
          const float* __restrict__ b1, const float* __restrict__ b2,
          const float* __restrict__ W3, const float* __restrict__ b3,
          float* __restrict__ out, int n_atoms) {
    extern __shared__ char sraw[];
    uint32_t sb = smem_u32(sraw);
    uint32_t wb = (sb + 127) & ~127u;
    char* base = sraw + (wb - sb);

    const int tid = threadIdx.x;
    const int gid = tid >> 8;                  // group 0 / 1
    const int gt  = tid & 255;                 // thread within group
    const int wn  = gt >> 5;                   // warp within group (n-strip)
    const int lane = tid & 31;
    const int g = lane >> 2, q = lane & 3;

    char*  s_A     = base + OFF_A + gid * A_G;
    char*  s_stage = base + OFF_STAGE + gid * STAGE_G;
    float* b1s     = (float*)(base + OFF_B1);
    float* b2s     = (float*)(base + OFF_B2);
    float* w3s     = (float*)(base + OFF_W3);
    float* molacc  = (float*)(base + OFF_MOL);
    float* rowsum  = (float*)(base + OFF_ROW) + gid * 32;
    const uint32_t mbar = wb + OFF_MBAR;
    const uint32_t A_u = wb + OFF_A + gid * A_G;
    const uint32_t W_u = wb + OFF_W;
    const uint32_t ST_u = wb + OFF_STAGE + gid * STAGE_G;
    const int barid = gid + 1;

    if (tid == 0) {
        MBARRIER_INIT(mbar, 1);
        FENCE_PROXY_ASYNC();
        MBARRIER_EXPECT_TX(mbar, 2 * WIMG_B);
        bulk_g2s(W_u, &g_Wimg[0][0], 2 * WIMG_B, mbar);
    }
    for (int i = tid; i < NMOL; i += NTHREADS) molacc[i] = 0.0f;
    if (gt < TM) rowsum[gt] = 0.0f;
    if (tid < FEAT) { b1s[tid] = b1[tid]; b2s[tid] = b2[tid]; w3s[tid] = W3[tid]; }
    const float b3v = *b3;

    const int stride = gridDim.x * 2 * TM;
    int row0 = (blockIdx.x * 2 + gid) * TM;
    issue_x(ST_u, X, row0, n_atoms, gt);
    __syncthreads();                            // init visible to all
    MBARRIER_WAIT_PARITY(mbar, 0);              // weights resident forever

    while (row0 < n_atoms) {
        CP_WAIT0();
        store_x(s_stage, s_A, gt);
        BAR_SYNC(barid);                        // A ready

        const int next_row0 = row0 + stride;
        if (next_row0 < n_atoms) issue_x(ST_u, X, next_row0, n_atoms, gt);

        // ---- layer 1 ----
        float acc[2][4][4];
#pragma unroll
        for (int mi = 0; mi < 2; mi++)
#pragma unroll
            for (int ni = 0; ni < 4; ni++)
#pragma unroll
                for (int j = 0; j < 4; j++) acc[mi][ni][j] = 0.0f;
        gemm_fp8(acc, A_u, W_u, wn, lane);
        BAR_SYNC(barid);                        // A consumed

        // ---- epilogue 1: bias + silu -> fp8 back into A ----
#pragma unroll
        for (int mi = 0; mi < 2; mi++) {
            int r0 = mi * 16 + g;
#pragma unroll
            for (int ni = 0; ni < 4; ni++) {
                int c0 = wn * 32 + ni * 8 + 2 * q;
                float bb0 = b1s[c0], bb1 = b1s[c0 + 1];
                unsigned short h0 = f2e4m3x2(fast_silu(acc[mi][ni][0] + bb0),
                                             fast_silu(acc[mi][ni][1] + bb1));
                unsigned short h1 = f2e4m3x2(fast_silu(acc[mi][ni][2] + bb0),
                                             fast_silu(acc[mi][ni][3] + bb1));
                *(unsigned short*)(s_A + swz(r0, c0))     = h0;
                *(unsigned short*)(s_A + swz(r0 + 8, c0)) = h1;
#pragma unroll
                for (int j = 0; j < 4; j++) acc[mi][ni][j] = 0.0f;
            }
        }
        BAR_SYNC(barid);                        // A2 ready

        // ---- layer 2 ----
        gemm_fp8(acc, A_u, W_u + WIMG_B, wn, lane);

        // ---- epilogue 2: bias + silu + dot(W3) ----
#pragma unroll
        for (int mi = 0; mi < 2; mi++) {
            float p0 = 0.0f, p1 = 0.0f;
#pragma unroll
            for (int ni = 0; ni < 4; ni++) {
                int c0 = wn * 32 + ni * 8 + 2 * q;
                float bb0 = b2s[c0], bb1 = b2s[c0 + 1];
                float w0 = w3s[c0], w1 = w3s[c0 + 1];
                p0 += fast_silu(acc[mi][ni][0] + bb0) * w0 + fast_silu(acc[mi][ni][1] + bb1) * w1;
                p1 += fast_silu(acc[mi][ni][2] + bb0) * w0 + fast_silu(acc[mi][ni][3] + bb1) * w1;
            }
            p0 += __shfl_xor_sync(0xffffffffu, p0, 1); p0 += __shfl_xor_sync(0xffffffffu, p0, 2);
            p1 += __shfl_xor_sync(0xffffffffu, p1, 1); p1 += __shfl_xor_sync(0xffffffffu, p1, 2);
            if (q == 0) {
                int r0 = mi * 16 + g;
                atomicAdd(&rowsum[r0], p0);
                atomicAdd(&rowsum[r0 + 8], p1);
            }
        }
        BAR_SYNC(barid);                        // rowsum ready; A consumed

        // ---- pooling ----
        if (gt < TM) {
            int grow = row0 + gt;
            if (grow < n_atoms) {
                int mol = load_mol(batch, grow);
                atomicAdd(&molacc[mol], rowsum[gt] + b3v);
            }
            rowsum[gt] = 0.0f;
        }
        row0 = next_row0;
    }

    __syncthreads();                            // both groups done
    for (int i = tid; i < NMOL; i += NTHREADS) {
        float v = molacc[i];
        if (v != 0.0f) atomicAdd(out + i, v * kScale);
    }
}

// ---------------------------------------------------------------------------
extern "C" void kernel_launch(void* const* d_in, const int* in_sizes, int n_in,
                              void* d_out, int out_size) {
    const float* atom_node = (const float*)d_in[0];
    const void*  batch     = d_in[1];
    const float* W1 = (const float*)d_in[2];
    const float* b1 = (const float*)d_in[3];
    const float* W2 = (const float*)d_in[4];
    const float* b2 = (const float*)d_in[5];
    const float* W3 = (const float*)d_in[6];
    const float* b3 = (const float*)d_in[7];
    float* out = (float*)d_out;
    const int n_atoms = in_sizes[1];

    prep<<<dim3(64, 2), 256>>>(W1, W2, batch, out);

    cudaFuncSetAttribute(fused_mlp, cudaFuncAttributeMaxDynamicSharedMemorySize, SMEM_BYTES);
    int ntiles = (n_atoms + 2 * TM - 1) / (2 * TM);
    int grid = ntiles < NCTA ? ntiles : NCTA;
    fused_mlp<<<grid, NTHREADS, SMEM_BYTES>>>(atom_node, batch, b1, b2, W3, b3, out, n_atoms);
}